// round 1
// baseline (speedup 1.0000x reference)
#include <cuda_runtime.h>
#include <math.h>

// Problem dims (fixed by the dataset)
#define B_DIM   16
#define L_DIM   1024
#define D_DIM   256
#define H_DIM   256
#define KWIN    16
#define R_TOTAL (B_DIM * L_DIM)   // 16384 independent GRU chains
#define G3      (3 * H_DIM)       // 768

// GEMM tile config
#define BM 128
#define BN 64
#define BK 16
#define TM 8
#define TN 4

// Scratch (allocation-free rule: device globals)
__device__ float g_G[R_TOTAL * G3];            // 48 MB: precomputed input projections (incl. b_ih)
__device__ float g_H[2][R_TOTAL * H_DIM];      // 2 x 16 MB ping-pong hidden state

__device__ __forceinline__ float sigm(float x) {
    return 1.0f / (1.0f + __expf(-x));
}

// ---------------------------------------------------------------------------
// Kernel 1: projection GEMM  G[row, g*256+n] = sum_d x[row,d]*W_ih[g*256+n,d] + b_ih
// A = x [16384, 256] (K-contig), B = W_ih [768, 256] (K-contig)  -> NT GEMM
// ---------------------------------------------------------------------------
__global__ __launch_bounds__(256) void proj_kernel(
    const float* __restrict__ X,
    const float* __restrict__ Wih,
    const float* __restrict__ bih)
{
    __shared__ __align__(16) float As[BK][BM];
    __shared__ __align__(16) float Bs[3][BK][BN];

    const int tid = threadIdx.x;
    const int tx = tid & 15, ty = tid >> 4;
    const int gm = blockIdx.x * BM;
    const int n0 = blockIdx.y * BN;
    const int lrow = tid >> 2;        // 0..63
    const int kq = (tid & 3) << 2;    // 0,4,8,12

    float acc[3][TM][TN];
#pragma unroll
    for (int g = 0; g < 3; g++)
#pragma unroll
        for (int i = 0; i < TM; i++)
#pragma unroll
            for (int j = 0; j < TN; j++) acc[g][i][j] = 0.0f;

    for (int k0 = 0; k0 < D_DIM; k0 += BK) {
#pragma unroll
        for (int i = 0; i < 2; i++) {
            int r = lrow + i * 64;
            float4 v = *(const float4*)&X[(size_t)(gm + r) * D_DIM + k0 + kq];
            As[kq + 0][r] = v.x; As[kq + 1][r] = v.y;
            As[kq + 2][r] = v.z; As[kq + 3][r] = v.w;
        }
#pragma unroll
        for (int g = 0; g < 3; g++) {
            float4 v = *(const float4*)&Wih[(size_t)(g * H_DIM + n0 + lrow) * D_DIM + k0 + kq];
            Bs[g][kq + 0][lrow] = v.x; Bs[g][kq + 1][lrow] = v.y;
            Bs[g][kq + 2][lrow] = v.z; Bs[g][kq + 3][lrow] = v.w;
        }
        __syncthreads();
#pragma unroll
        for (int kk = 0; kk < BK; kk++) {
            float a[TM];
            *(float4*)&a[0] = *(const float4*)&As[kk][ty * TM];
            *(float4*)&a[4] = *(const float4*)&As[kk][ty * TM + 4];
#pragma unroll
            for (int g = 0; g < 3; g++) {
                float b[TN];
                *(float4*)&b[0] = *(const float4*)&Bs[g][kk][tx * TN];
#pragma unroll
                for (int i = 0; i < TM; i++)
#pragma unroll
                    for (int j = 0; j < TN; j++)
                        acc[g][i][j] = fmaf(a[i], b[j], acc[g][i][j]);
            }
        }
        __syncthreads();
    }

    const int col = n0 + tx * TN;
#pragma unroll
    for (int i = 0; i < TM; i++) {
        int row = gm + ty * TM + i;
#pragma unroll
        for (int g = 0; g < 3; g++) {
            float4 bv = *(const float4*)&bih[g * H_DIM + col];
            float o[4];
#pragma unroll
            for (int j = 0; j < TN; j++) o[j] = acc[g][i][j] + ((const float*)&bv)[j];
            *(float4*)&g_G[(size_t)row * G3 + g * H_DIM + col] =
                make_float4(o[0], o[1], o[2], o[3]);
        }
    }
}

// ---------------------------------------------------------------------------
// Kernel 2: window step t=0 (h=0 so gh=0; pure elementwise)
// h1 = (1-z)*tanh(gi_n + r*b_hh_n),  r=sig(gi_r+b_hh_r), z=sig(gi_z+b_hh_z)
// ---------------------------------------------------------------------------
__global__ __launch_bounds__(256) void step0_kernel(
    const float* __restrict__ bih,
    const float* __restrict__ bhh)
{
    const int row = blockIdx.x;
    const int col = threadIdx.x;
    const int l = row & (L_DIM - 1);
    const int src = l - (KWIN - 1);

    float gir, giz, gin;
    if (src >= 0) {
        const float* Gp = &g_G[(size_t)(row - l + src) * G3 + col];
        gir = Gp[0]; giz = Gp[H_DIM]; gin = Gp[2 * H_DIM];
    } else {
        gir = bih[col]; giz = bih[col + H_DIM]; gin = bih[col + 2 * H_DIM];
    }
    float r  = sigm(gir + bhh[col]);
    float z  = sigm(giz + bhh[col + H_DIM]);
    float nn = tanhf(gin + r * bhh[col + 2 * H_DIM]);
    g_H[0][(size_t)row * H_DIM + col] = (1.0f - z) * nn;
}

// ---------------------------------------------------------------------------
// Kernel 3: fused step GEMM + GRU update for window step t (1..15)
//   gh = h @ W_hh^T  (3 gates fused),  then GRU update, write H_out (or d_out)
// ---------------------------------------------------------------------------
__global__ __launch_bounds__(256) void step_kernel(
    const float* __restrict__ Whh,
    const float* __restrict__ bih,
    const float* __restrict__ bhh,
    int t, int in_idx, float* __restrict__ fin)
{
    const float* __restrict__ Hin = g_H[in_idx];
    float* __restrict__ Hout = fin ? fin : g_H[in_idx ^ 1];

    __shared__ __align__(16) float As[BK][BM];
    __shared__ __align__(16) float Bs[3][BK][BN];

    const int tid = threadIdx.x;
    const int tx = tid & 15, ty = tid >> 4;
    const int gm = blockIdx.x * BM;
    const int n0 = blockIdx.y * BN;
    const int lrow = tid >> 2;
    const int kq = (tid & 3) << 2;

    float acc[3][TM][TN];
#pragma unroll
    for (int g = 0; g < 3; g++)
#pragma unroll
        for (int i = 0; i < TM; i++)
#pragma unroll
            for (int j = 0; j < TN; j++) acc[g][i][j] = 0.0f;

    for (int k0 = 0; k0 < H_DIM; k0 += BK) {
#pragma unroll
        for (int i = 0; i < 2; i++) {
            int r = lrow + i * 64;
            float4 v = *(const float4*)&Hin[(size_t)(gm + r) * H_DIM + k0 + kq];
            As[kq + 0][r] = v.x; As[kq + 1][r] = v.y;
            As[kq + 2][r] = v.z; As[kq + 3][r] = v.w;
        }
#pragma unroll
        for (int g = 0; g < 3; g++) {
            float4 v = *(const float4*)&Whh[(size_t)(g * H_DIM + n0 + lrow) * H_DIM + k0 + kq];
            Bs[g][kq + 0][lrow] = v.x; Bs[g][kq + 1][lrow] = v.y;
            Bs[g][kq + 2][lrow] = v.z; Bs[g][kq + 3][lrow] = v.w;
        }
        __syncthreads();
#pragma unroll
        for (int kk = 0; kk < BK; kk++) {
            float a[TM];
            *(float4*)&a[0] = *(const float4*)&As[kk][ty * TM];
            *(float4*)&a[4] = *(const float4*)&As[kk][ty * TM + 4];
#pragma unroll
            for (int g = 0; g < 3; g++) {
                float b[TN];
                *(float4*)&b[0] = *(const float4*)&Bs[g][kk][tx * TN];
#pragma unroll
                for (int i = 0; i < TM; i++)
#pragma unroll
                    for (int j = 0; j < TN; j++)
                        acc[g][i][j] = fmaf(a[i], b[j], acc[g][i][j]);
            }
        }
        __syncthreads();
    }

    // GRU update epilogue
    const int col = n0 + tx * TN;
    float4 bh_r = *(const float4*)&bhh[col];
    float4 bh_z = *(const float4*)&bhh[col + H_DIM];
    float4 bh_n = *(const float4*)&bhh[col + 2 * H_DIM];
    float4 bi_r = *(const float4*)&bih[col];
    float4 bi_z = *(const float4*)&bih[col + H_DIM];
    float4 bi_n = *(const float4*)&bih[col + 2 * H_DIM];

#pragma unroll
    for (int i = 0; i < TM; i++) {
        int row = gm + ty * TM + i;
        int l = row & (L_DIM - 1);
        int src = l + t - (KWIN - 1);
        float4 gr, gz, gn;
        if (src >= 0) {
            const float* Gp = &g_G[(size_t)(row - l + src) * G3 + col];
            gr = *(const float4*)(Gp);
            gz = *(const float4*)(Gp + H_DIM);
            gn = *(const float4*)(Gp + 2 * H_DIM);
        } else {
            gr = bi_r; gz = bi_z; gn = bi_n;
        }
        float4 hold = *(const float4*)&Hin[(size_t)row * H_DIM + col];
        float o[4];
#pragma unroll
        for (int j = 0; j < TN; j++) {
            float ghr = acc[0][i][j] + ((const float*)&bh_r)[j];
            float ghz = acc[1][i][j] + ((const float*)&bh_z)[j];
            float ghn = acc[2][i][j] + ((const float*)&bh_n)[j];
            float r  = sigm(((const float*)&gr)[j] + ghr);
            float z  = sigm(((const float*)&gz)[j] + ghz);
            float nn = tanhf(((const float*)&gn)[j] + r * ghn);
            o[j] = (1.0f - z) * nn + z * ((const float*)&hold)[j];
        }
        *(float4*)&Hout[(size_t)row * H_DIM + col] = make_float4(o[0], o[1], o[2], o[3]);
    }
}

// ---------------------------------------------------------------------------
// Launch: proj -> step0 -> 15 x fused step (ping-pong, last writes d_out)
// ---------------------------------------------------------------------------
extern "C" void kernel_launch(void* const* d_in, const int* in_sizes, int n_in,
                              void* d_out, int out_size)
{
    const float* x   = (const float*)d_in[0];
    const float* Wih = (const float*)d_in[1];
    const float* Whh = (const float*)d_in[2];
    const float* bih = (const float*)d_in[3];
    const float* bhh = (const float*)d_in[4];
    float* out = (float*)d_out;

    dim3 grid(R_TOTAL / BM, H_DIM / BN);   // (128, 4)
    proj_kernel<<<grid, 256>>>(x, Wih, bih);
    step0_kernel<<<R_TOTAL, 256>>>(bih, bhh);
    for (int t = 1; t < KWIN; t++) {
        int in_idx = (t - 1) & 1;
        float* fin = (t == KWIN - 1) ? out : nullptr;
        step_kernel<<<grid, 256>>>(Whh, bih, bhh, t, in_idx, fin);
    }
}